// round 14
// baseline (speedup 1.0000x reference)
#include <cuda_runtime.h>
#include <cuda_bf16.h>
#include <math.h>
#include <stdint.h>

#define MTOT 32768
#define CDIM 1024
#define HDIM 4096
#define EDIM 8
#define NXSL (HDIM / 64)           // 64 hdim slices (GEMM1 bx count)

// ---- GEMM1 tiling: 128x64 CTA tile, BK=32, 8 warps of 32x32, 3 stages, 2 CTAs/SM ----
#define ROWB   80                  // 32 bf16 = 64B + 16B pad (ldsm conflict-free, proven R6/R8)
#define SM_W2  0                   // 2 KB: w2tq slice [64][8] fp32
#define SM_ST  2048                // stages start
#define OFF_AH 0                   // 128 rows * 80B = 10240
#define OFF_AL 10240
#define OFF_BH 20480               // 64 rows * 80B = 5120
#define OFF_BL 25600
#define STAGE  30720
#define SMEM_TOT (SM_ST + 3 * STAGE)   // 94208 bytes -> 2 CTAs/SM fit (188416 < 228KB)

// ---------------- device globals (no runtime allocation allowed) ----------------
__device__ __nv_bfloat16 g_xh[(size_t)MTOT*CDIM], g_xl[(size_t)MTOT*CDIM];   // x split
__device__ __nv_bfloat16 g_w1h[(size_t)HDIM*CDIM], g_w1l[(size_t)HDIM*CDIM]; // W1^T split [N][K]
__device__ float g_w2tqf[(size_t)HDIM*EDIM];                                  // (W2@tq^T) fp32 [H][E]
__device__ float g_b2tq[EDIM];
__device__ float g_spart[(size_t)NXSL*MTOT*EDIM];                             // partial scores per hdim-slice
__device__ float g_scores[(size_t)MTOT*EDIM];

// ---------------- PTX helpers (base sm_100-compatible PTX only) ----------------
__device__ __forceinline__ uint32_t smem_u32(const void* p) {
    uint32_t a;
    asm("{ .reg .u64 t; cvta.to.shared.u64 t, %1; cvt.u32.u64 %0, t; }" : "=r"(a) : "l"(p));
    return a;
}
__device__ __forceinline__ void cpa16(uint32_t d, const void* s) {
    asm volatile("cp.async.cg.shared.global [%0], [%1], 16;" :: "r"(d), "l"(s));
}
#define CP_COMMIT() asm volatile("cp.async.commit_group;" ::: "memory")
#define CP_WAIT1()  asm volatile("cp.async.wait_group 1;" ::: "memory")

__device__ __forceinline__ void ldsm4(uint32_t* r, uint32_t a) {
    asm volatile("ldmatrix.sync.aligned.m8n8.x4.shared.b16 {%0,%1,%2,%3}, [%4];"
        : "=r"(r[0]), "=r"(r[1]), "=r"(r[2]), "=r"(r[3]) : "r"(a));
}
__device__ __forceinline__ void mma16816(float* c, const uint32_t* a, const uint32_t* b) {
    asm volatile("mma.sync.aligned.m16n8k16.row.col.f32.bf16.bf16.f32 "
        "{%0,%1,%2,%3}, {%4,%5,%6,%7}, {%8,%9}, {%0,%1,%2,%3};"
        : "+f"(c[0]), "+f"(c[1]), "+f"(c[2]), "+f"(c[3])
        : "r"(a[0]), "r"(a[1]), "r"(a[2]), "r"(a[3]), "r"(b[0]), "r"(b[1]));
}

__device__ __forceinline__ float gelu_exact(float v) {
    return 0.5f * v * (1.0f + erff(v * 0.70710678118654752440f));
}

// ---------------- prep kernels (unchanged from R12 pass) ----------------
__global__ void __launch_bounds__(256)
split_x_kernel(const float* __restrict__ in, __nv_bfloat16* __restrict__ hi,
               __nv_bfloat16* __restrict__ lo, int n4)
{
    int i = blockIdx.x * blockDim.x + threadIdx.x;
    if (i >= n4) return;
    float4 v = ((const float4*)in)[i];
    __nv_bfloat16 h0 = __float2bfloat16(v.x), h1 = __float2bfloat16(v.y);
    __nv_bfloat16 h2 = __float2bfloat16(v.z), h3 = __float2bfloat16(v.w);
    __nv_bfloat16 l0 = __float2bfloat16(v.x - __bfloat162float(h0));
    __nv_bfloat16 l1 = __float2bfloat16(v.y - __bfloat162float(h1));
    __nv_bfloat16 l2 = __float2bfloat16(v.z - __bfloat162float(h2));
    __nv_bfloat16 l3 = __float2bfloat16(v.w - __bfloat162float(h3));
    uint2 hh, ll;
    hh.x = (uint32_t)__bfloat16_as_ushort(h0) | ((uint32_t)__bfloat16_as_ushort(h1) << 16);
    hh.y = (uint32_t)__bfloat16_as_ushort(h2) | ((uint32_t)__bfloat16_as_ushort(h3) << 16);
    ll.x = (uint32_t)__bfloat16_as_ushort(l0) | ((uint32_t)__bfloat16_as_ushort(l1) << 16);
    ll.y = (uint32_t)__bfloat16_as_ushort(l2) | ((uint32_t)__bfloat16_as_ushort(l3) << 16);
    ((uint2*)hi)[i] = hh;
    ((uint2*)lo)[i] = ll;
}

__global__ void __launch_bounds__(1024)
tsplit_kernel(const float* __restrict__ W, __nv_bfloat16* __restrict__ Th,
              __nv_bfloat16* __restrict__ Tl, int K, int N)
{
    __shared__ float t[32][33];
    int n0 = blockIdx.x * 32, k0 = blockIdx.y * 32;
    t[threadIdx.y][threadIdx.x] = W[(size_t)(k0 + threadIdx.y) * N + n0 + threadIdx.x];
    __syncthreads();
    float v = t[threadIdx.x][threadIdx.y];
    int n = n0 + threadIdx.y, k = k0 + threadIdx.x;
    __nv_bfloat16 h = __float2bfloat16(v);
    Th[(size_t)n * K + k] = h;
    Tl[(size_t)n * K + k] = __float2bfloat16(v - __bfloat162float(h));
}

__global__ void __launch_bounds__(256)
w2tq_kernel(const float* __restrict__ W2, const float* __restrict__ tq,
            const float* __restrict__ b2,
            float* __restrict__ Wf, float* __restrict__ b2tq)
{
    __shared__ float tqs[EDIM][CDIM];
    for (int i = threadIdx.x; i < EDIM * CDIM; i += blockDim.x)
        ((float*)tqs)[i] = tq[i];
    __syncthreads();

    const int lane = threadIdx.x & 31;
    const int warp = threadIdx.x >> 5;

    if (blockIdx.x < 512) {
        const int k = blockIdx.x * 8 + warp;
        const float* wr = W2 + (size_t)k * CDIM;
        float acc[EDIM];
#pragma unroll
        for (int e = 0; e < EDIM; e++) acc[e] = 0.f;
        for (int c = lane; c < CDIM; c += 32) {
            float wv = wr[c];
#pragma unroll
            for (int e = 0; e < EDIM; e++) acc[e] += wv * tqs[e][c];
        }
#pragma unroll
        for (int off = 16; off >= 1; off >>= 1)
#pragma unroll
            for (int e = 0; e < EDIM; e++)
                acc[e] += __shfl_xor_sync(0xffffffffu, acc[e], off);
        if (lane < EDIM) {
            float v = 0.f;
#pragma unroll
            for (int e = 0; e < EDIM; e++) if (lane == e) v = acc[e];
            Wf[(size_t)k * EDIM + lane] = v;
        }
    } else {
        if (warp < EDIM) {
            float a = 0.f;
            for (int c = lane; c < CDIM; c += 32) a += b2[c] * tqs[warp][c];
#pragma unroll
            for (int off = 16; off >= 1; off >>= 1)
                a += __shfl_xor_sync(0xffffffffu, a, off);
            if (lane == 0) b2tq[warp] = a;
        }
    }
}

// ---------------- GEMM1 stage loader (256 threads, BK=32) ----------------
// A: 128 rows x 4 16B-chunks = 512 chunks per array (2 per thread)
// B: 64 rows  x 4 16B-chunks = 256 chunks per array (1 per thread)
__device__ __forceinline__ void issue_stage(
    const __nv_bfloat16* __restrict__ Ah, const __nv_bfloat16* __restrict__ Al,
    const __nv_bfloat16* __restrict__ Bh, const __nv_bfloat16* __restrict__ Bl,
    uint32_t stage_base, int kblk, int tid)
{
    const size_t kb = (size_t)kblk * 32;
#pragma unroll
    for (int j = 0; j < 2; j++) {
        int idx = tid + j * 256;
        int r = idx >> 2, ch = idx & 3;
        uint32_t so = stage_base + r * ROWB + ch * 16;
        size_t go = (size_t)r * CDIM + kb + ch * 8;
        cpa16(so + OFF_AH, Ah + go);
        cpa16(so + OFF_AL, Al + go);
    }
    {
        int r = tid >> 2, ch = tid & 3;
        uint32_t so = stage_base + r * ROWB + ch * 16;
        size_t go = (size_t)r * CDIM + kb + ch * 8;
        cpa16(so + OFF_BH, Bh + go);
        cpa16(so + OFF_BL, Bl + go);
    }
}

// ---------------- fused GEMM1 + scores partial, 2 CTAs/SM ----------------
// 256 threads, 8 warps (4 warp_m x 2 warp_n), warp tile 32x32, CTA tile 128x64.
__global__ void __launch_bounds__(256, 2)
gemm_fused(const __nv_bfloat16* __restrict__ Ah, const __nv_bfloat16* __restrict__ Al,
           const __nv_bfloat16* __restrict__ Bh, const __nv_bfloat16* __restrict__ Bl,
           const float* __restrict__ bias, const float* __restrict__ w2tqf,
           float* __restrict__ spart)
{
    extern __shared__ __align__(128) char smem[];
    const uint32_t sb = smem_u32(smem) + SM_ST;
    float* w2s = (float*)(smem + SM_W2);        // [64][8]
    const int tid = threadIdx.x;
    const int wid = tid >> 5, lane = tid & 31;
    const int warp_m = wid >> 1, warp_n = wid & 1;   // 4 x 2 warp grid, 32x32 per warp
    const int bx = blockIdx.x, by = blockIdx.y;
    constexpr int NCH = CDIM / 32;

    const __nv_bfloat16* At_h = Ah + (size_t)(by * 128) * CDIM;
    const __nv_bfloat16* At_l = Al + (size_t)(by * 128) * CDIM;
    const __nv_bfloat16* Bt_h = Bh + (size_t)(bx * 64) * CDIM;
    const __nv_bfloat16* Bt_l = Bl + (size_t)(bx * 64) * CDIM;

    // load this CTA's w2tq slice (64 cols x 8 experts, fp32)
    {
        const float4* src = (const float4*)(w2tqf + (size_t)(bx * 64) * EDIM);
        float4* dst = (float4*)w2s;
        for (int i = tid; i < 64 * EDIM / 4; i += 256) dst[i] = src[i];
    }

    float acc[2][4][4];
#pragma unroll
    for (int i = 0; i < 2; i++)
#pragma unroll
        for (int j = 0; j < 4; j++)
#pragma unroll
            for (int k = 0; k < 4; k++) acc[i][j][k] = 0.f;

    issue_stage(At_h, At_l, Bt_h, Bt_l, sb + 0 * STAGE, 0, tid);
    CP_COMMIT();
    issue_stage(At_h, At_l, Bt_h, Bt_l, sb + 1 * STAGE, 1, tid);
    CP_COMMIT();
    CP_WAIT1();
    __syncthreads();

    const int aRow = warp_m * 32 + (lane & 15);
    const int aCol16 = (lane >> 4) * 16;
    const int bRow = warp_n * 32 + (lane & 7) + ((lane >> 4) << 3);
    const int bCol16 = ((lane >> 3) & 1) * 16;

#pragma unroll 1
    for (int c = 0; c < NCH; c++) {
        const uint32_t st = sb + (c % 3) * STAGE;
        if (c + 2 < NCH)
            issue_stage(At_h, At_l, Bt_h, Bt_l, sb + ((c + 2) % 3) * STAGE, c + 2, tid);
        CP_COMMIT();

#pragma unroll
        for (int ks = 0; ks < 2; ks++) {
            uint32_t ahf[2][4], alf[2][4], bhf[2][4], blf[2][4];
#pragma unroll
            for (int mt = 0; mt < 2; mt++) {
                uint32_t ad = st + OFF_AH + (uint32_t)(aRow + mt * 16) * ROWB + aCol16 + ks * 32;
                ldsm4(ahf[mt], ad);
                ldsm4(alf[mt], ad + (OFF_AL - OFF_AH));
            }
#pragma unroll
            for (int nh = 0; nh < 2; nh++) {
                uint32_t bd = st + OFF_BH + (uint32_t)(bRow + nh * 16) * ROWB + bCol16 + ks * 32;
                ldsm4(bhf[nh], bd);
                ldsm4(blf[nh], bd + (OFF_BL - OFF_BH));
            }
#pragma unroll
            for (int mt = 0; mt < 2; mt++)
#pragma unroll
                for (int nt = 0; nt < 4; nt++) {
                    const uint32_t* bh2 = &bhf[nt >> 1][(nt & 1) * 2];
                    const uint32_t* bl2 = &blf[nt >> 1][(nt & 1) * 2];
                    mma16816(acc[mt][nt], ahf[mt], bh2);
                    mma16816(acc[mt][nt], ahf[mt], bl2);
                    mma16816(acc[mt][nt], alf[mt], bh2);
                }
        }
        CP_WAIT1();
        __syncthreads();
    }

    // ---- fused epilogue: gelu + partial scores, no h stores ----
    float p[4][EDIM];
#pragma unroll
    for (int r = 0; r < 4; r++)
#pragma unroll
        for (int e = 0; e < EDIM; e++) p[r][e] = 0.f;

#pragma unroll
    for (int mt = 0; mt < 2; mt++)
#pragma unroll
        for (int nt = 0; nt < 4; nt++) {
            const int col_local = warp_n * 32 + nt * 8 + (lane & 3) * 2;
            const int col = bx * 64 + col_local;
            const float bv0 = __ldg(bias + col), bv1 = __ldg(bias + col + 1);
            const float* w0 = w2s + col_local * EDIM;
            const float* w1 = w2s + (col_local + 1) * EDIM;
#pragma unroll
            for (int half = 0; half < 2; half++) {
                const int ri = mt * 2 + half;
                float v0 = gelu_exact(acc[mt][nt][half * 2 + 0] + bv0);
                float v1 = gelu_exact(acc[mt][nt][half * 2 + 1] + bv1);
#pragma unroll
                for (int e = 0; e < EDIM; e++)
                    p[ri][e] += v0 * w0[e] + v1 * w1[e];
            }
        }

    // reduce across the 4 lanes of each quad (disjoint cols, same rows)
#pragma unroll
    for (int off = 1; off <= 2; off <<= 1)
#pragma unroll
        for (int r = 0; r < 4; r++)
#pragma unroll
            for (int e = 0; e < EDIM; e++)
                p[r][e] += __shfl_xor_sync(0xffffffffu, p[r][e], off);

    // cross-warp_n reduction through (now free) stage smem: sp[2][128][8]
    float* sp = (float*)(smem + SM_ST);
    __syncthreads();   // all mainloop smem reads complete; safe to reuse
    if ((lane & 3) == 0) {
#pragma unroll
        for (int ri = 0; ri < 4; ri++) {
            const int mt = ri >> 1, half = ri & 1;
            const int row_local = warp_m * 32 + mt * 16 + (lane >> 2) + half * 8;
#pragma unroll
            for (int e = 0; e < EDIM; e++)
                sp[(warp_n * 128 + row_local) * EDIM + e] = p[ri][e];
        }
    }
    __syncthreads();

    // final: sum 2 warp_n slices, write partial to g_spart[bx]
    for (int idx = tid; idx < 128 * EDIM; idx += 256) {
        float s = sp[idx] + sp[128 * EDIM + idx];
        spart[((size_t)bx * MTOT + by * 128) * EDIM + idx] = s;
    }
}

// ---------------- deterministic reduce over hdim slices ----------------
__global__ void __launch_bounds__(256)
reduce_scores(const float* __restrict__ spart, float* __restrict__ S, int n)
{
    int idx = blockIdx.x * blockDim.x + threadIdx.x;
    if (idx >= n) return;
    float s = 0.f;
#pragma unroll
    for (int b = 0; b < NXSL; b++)
        s += spart[(size_t)b * n + idx];
    S[idx] = s;
}

// ---------------- routing tail (unchanged from R12 pass) ----------------
__global__ void __launch_bounds__(256)
route_kernel(const float* __restrict__ S, const float* __restrict__ x,
             const float* __restrict__ noise,
             const float* __restrict__ nw, const float* __restrict__ nb,
             const float* __restrict__ temp_p, const float* __restrict__ b2tq,
             float* __restrict__ out_router, float* __restrict__ out_idx, int M)
{
    __shared__ float nws[CDIM];
    __shared__ float b2s[EDIM];
    for (int i = threadIdx.x; i < CDIM; i += blockDim.x) nws[i] = nw[i];
    if (threadIdx.x < EDIM) b2s[threadIdx.x] = b2tq[threadIdx.x];
    __syncthreads();

    const int lane = threadIdx.x & 31;
    const int warp = threadIdx.x >> 5;
    const float temp = *temp_p;
    const float nbv  = *nb;

    for (int t = blockIdx.x * 8 + warp; t < M; t += gridDim.x * 8) {
        const float* xr = x + (size_t)t * CDIM;
        float accg = 0.f;
        for (int j = lane; j < CDIM; j += 32) accg += xr[j] * nws[j];
#pragma unroll
        for (int off = 16; off >= 1; off >>= 1)
            accg += __shfl_xor_sync(0xffffffffu, accg, off);

        float gate = 1.f / (1.f + expf(-(accg + nbv)));

        const float4* sp = (const float4*)(S + (size_t)t * EDIM);
        float4 s0 = sp[0], s1 = sp[1];
        float sc[EDIM] = { s0.x, s0.y, s0.z, s0.w, s1.x, s1.y, s1.z, s1.w };

        float noisy[EDIM];
#pragma unroll
        for (int e = 0; e < EDIM; e++)
            noisy[e] = sc[e] + b2s[e] + temp * noise[(size_t)t * EDIM + e] * gate;

        int i0 = 0; float v0 = noisy[0];
#pragma unroll
        for (int e = 1; e < EDIM; e++)
            if (noisy[e] > v0) { v0 = noisy[e]; i0 = e; }
        int i1 = -1; float v1 = -INFINITY;
#pragma unroll
        for (int e = 0; e < EDIM; e++)
            if (e != i0 && noisy[e] > v1) { v1 = noisy[e]; i1 = e; }

        float inv = 1.f / (temp + 1e-6f);
        float e1 = expf((v1 - v0) * inv);
        float denom = 1.f + e1;
        float p0 = 1.f / denom;
        float p1 = e1 / denom;

        if (lane < EDIM) {
            float pv = (lane == i0) ? p0 : ((lane == i1) ? p1 : 0.f);
            out_router[(size_t)t * EDIM + lane] = pv;
        }
        if (out_idx != nullptr && lane == 0) {
            out_idx[(size_t)t * 2 + 0] = (float)i0;
            out_idx[(size_t)t * 2 + 1] = (float)i1;
        }
    }
}

// ---------------- launch ----------------
extern "C" void kernel_launch(void* const* d_in, const int* in_sizes, int n_in,
                              void* d_out, int out_size)
{
    const float* x     = (const float*)d_in[0];
    const float* noise = (const float*)d_in[1];
    const float* W1    = (const float*)d_in[2];
    const float* b1    = (const float*)d_in[3];
    const float* W2    = (const float*)d_in[4];
    const float* b2    = (const float*)d_in[5];
    const float* tq    = (const float*)d_in[6];
    const float* nw    = (const float*)d_in[7];
    const float* nb    = (const float*)d_in[8];
    const float* temp  = (const float*)d_in[9];

    const int M = in_sizes[0] / CDIM;   // 32768

    __nv_bfloat16 *xh, *xl, *w1h, *w1l;
    float *w2tqf, *scores, *spart, *b2tqp;
    cudaGetSymbolAddress((void**)&xh,  g_xh);    cudaGetSymbolAddress((void**)&xl,  g_xl);
    cudaGetSymbolAddress((void**)&w1h, g_w1h);   cudaGetSymbolAddress((void**)&w1l, g_w1l);
    cudaGetSymbolAddress((void**)&w2tqf, g_w2tqf);
    cudaGetSymbolAddress((void**)&scores, g_scores);
    cudaGetSymbolAddress((void**)&spart, g_spart);
    cudaGetSymbolAddress((void**)&b2tqp, g_b2tq);

    cudaFuncSetAttribute(gemm_fused, cudaFuncAttributeMaxDynamicSharedMemorySize, SMEM_TOT);

    // prep: split x, transpose+split W1, fold W2 into tq (fp32)
    int n4 = (M * CDIM) / 4;
    split_x_kernel<<<(n4 + 255) / 256, 256>>>(x, xh, xl, n4);
    tsplit_kernel<<<dim3(HDIM / 32, CDIM / 32), dim3(32, 32)>>>(W1, w1h, w1l, CDIM, HDIM);
    w2tq_kernel<<<513, 256>>>(W2, tq, b2, w2tqf, b2tqp);

    // fused GEMM1 + scores partials, 2 CTAs/SM
    gemm_fused<<<dim3(HDIM / 64, M / 128), 256, SMEM_TOT>>>(
        xh, xl, w1h, w1l, b1, w2tqf, spart);

    // deterministic reduction over the 64 hdim slices
    reduce_scores<<<(M * EDIM + 255) / 256, 256>>>(spart, scores, M * EDIM);

    float* out = (float*)d_out;
    float* out_router = out;
    float* out_idx = nullptr;
    if (out_size >= M * EDIM + M * 2)
        out_idx = out + (size_t)M * EDIM;

    route_kernel<<<M / 8, 256>>>(scores, x, noise, nw, nb, temp, b2tqp,
                                 out_router, out_idx, M);
}

// round 15
// speedup vs baseline: 1.0819x; 1.0819x over previous
#include <cuda_runtime.h>
#include <cuda_bf16.h>
#include <math.h>
#include <stdint.h>

#define MTOT 32768
#define CDIM 1024
#define HDIM 4096
#define EDIM 8
#define NXSL (HDIM / 256)          // 16 hdim slices (GEMM1 bx count)

// ---- GEMM1 tiling: 128x256 CTA tile, BK=32, 16 warps of 32x64, 3 cp.async stages ----
#define ROWB   80                  // 32 bf16 = 64B + 16B pad (ldsm conflict-free, proven)
#define SM_W2  0                   // 8 KB: w2tq slice [256][8] fp32
#define SM_ST  8192                // stages start
#define OFF_AH 0                   // A: 128 rows * 80B = 10240
#define OFF_AL 10240
#define OFF_BH 20480               // B: 256 rows * 80B = 20480
#define OFF_BL 40960
#define STAGE  61440
#define SMEM_TOT (SM_ST + 3 * STAGE)   // 192512 bytes (1 CTA/SM)

// ---------------- device globals (no runtime allocation allowed) ----------------
__device__ __nv_bfloat16 g_xh[(size_t)MTOT*CDIM], g_xl[(size_t)MTOT*CDIM];   // x split
__device__ __nv_bfloat16 g_w1h[(size_t)HDIM*CDIM], g_w1l[(size_t)HDIM*CDIM]; // W1^T split [N][K]
__device__ float g_w2tqf[(size_t)HDIM*EDIM];                                  // (W2@tq^T) fp32 [H][E]
__device__ float g_b2tq[EDIM];
__device__ float g_spart[(size_t)NXSL*MTOT*EDIM];                             // partial scores per hdim-slice
__device__ float g_scores[(size_t)MTOT*EDIM];

// ---------------- PTX helpers (base sm_100-compatible PTX only) ----------------
__device__ __forceinline__ uint32_t smem_u32(const void* p) {
    uint32_t a;
    asm("{ .reg .u64 t; cvta.to.shared.u64 t, %1; cvt.u32.u64 %0, t; }" : "=r"(a) : "l"(p));
    return a;
}
__device__ __forceinline__ void cpa16(uint32_t d, const void* s) {
    asm volatile("cp.async.cg.shared.global [%0], [%1], 16;" :: "r"(d), "l"(s));
}
#define CP_COMMIT() asm volatile("cp.async.commit_group;" ::: "memory")
#define CP_WAIT1()  asm volatile("cp.async.wait_group 1;" ::: "memory")

__device__ __forceinline__ void ldsm4(uint32_t* r, uint32_t a) {
    asm volatile("ldmatrix.sync.aligned.m8n8.x4.shared.b16 {%0,%1,%2,%3}, [%4];"
        : "=r"(r[0]), "=r"(r[1]), "=r"(r[2]), "=r"(r[3]) : "r"(a));
}
__device__ __forceinline__ void mma16816(float* c, const uint32_t* a, const uint32_t* b) {
    asm volatile("mma.sync.aligned.m16n8k16.row.col.f32.bf16.bf16.f32 "
        "{%0,%1,%2,%3}, {%4,%5,%6,%7}, {%8,%9}, {%0,%1,%2,%3};"
        : "+f"(c[0]), "+f"(c[1]), "+f"(c[2]), "+f"(c[3])
        : "r"(a[0]), "r"(a[1]), "r"(a[2]), "r"(a[3]), "r"(b[0]), "r"(b[1]));
}

__device__ __forceinline__ float gelu_exact(float v) {
    return 0.5f * v * (1.0f + erff(v * 0.70710678118654752440f));
}

// ---------------- prep kernels (unchanged from R12 pass) ----------------
__global__ void __launch_bounds__(256)
split_x_kernel(const float* __restrict__ in, __nv_bfloat16* __restrict__ hi,
               __nv_bfloat16* __restrict__ lo, int n4)
{
    int i = blockIdx.x * blockDim.x + threadIdx.x;
    if (i >= n4) return;
    float4 v = ((const float4*)in)[i];
    __nv_bfloat16 h0 = __float2bfloat16(v.x), h1 = __float2bfloat16(v.y);
    __nv_bfloat16 h2 = __float2bfloat16(v.z), h3 = __float2bfloat16(v.w);
    __nv_bfloat16 l0 = __float2bfloat16(v.x - __bfloat162float(h0));
    __nv_bfloat16 l1 = __float2bfloat16(v.y - __bfloat162float(h1));
    __nv_bfloat16 l2 = __float2bfloat16(v.z - __bfloat162float(h2));
    __nv_bfloat16 l3 = __float2bfloat16(v.w - __bfloat162float(h3));
    uint2 hh, ll;
    hh.x = (uint32_t)__bfloat16_as_ushort(h0) | ((uint32_t)__bfloat16_as_ushort(h1) << 16);
    hh.y = (uint32_t)__bfloat16_as_ushort(h2) | ((uint32_t)__bfloat16_as_ushort(h3) << 16);
    ll.x = (uint32_t)__bfloat16_as_ushort(l0) | ((uint32_t)__bfloat16_as_ushort(l1) << 16);
    ll.y = (uint32_t)__bfloat16_as_ushort(l2) | ((uint32_t)__bfloat16_as_ushort(l3) << 16);
    ((uint2*)hi)[i] = hh;
    ((uint2*)lo)[i] = ll;
}

__global__ void __launch_bounds__(1024)
tsplit_kernel(const float* __restrict__ W, __nv_bfloat16* __restrict__ Th,
              __nv_bfloat16* __restrict__ Tl, int K, int N)
{
    __shared__ float t[32][33];
    int n0 = blockIdx.x * 32, k0 = blockIdx.y * 32;
    t[threadIdx.y][threadIdx.x] = W[(size_t)(k0 + threadIdx.y) * N + n0 + threadIdx.x];
    __syncthreads();
    float v = t[threadIdx.x][threadIdx.y];
    int n = n0 + threadIdx.y, k = k0 + threadIdx.x;
    __nv_bfloat16 h = __float2bfloat16(v);
    Th[(size_t)n * K + k] = h;
    Tl[(size_t)n * K + k] = __float2bfloat16(v - __bfloat162float(h));
}

__global__ void __launch_bounds__(256)
w2tq_kernel(const float* __restrict__ W2, const float* __restrict__ tq,
            const float* __restrict__ b2,
            float* __restrict__ Wf, float* __restrict__ b2tq)
{
    __shared__ float tqs[EDIM][CDIM];
    for (int i = threadIdx.x; i < EDIM * CDIM; i += blockDim.x)
        ((float*)tqs)[i] = tq[i];
    __syncthreads();

    const int lane = threadIdx.x & 31;
    const int warp = threadIdx.x >> 5;

    if (blockIdx.x < 512) {
        const int k = blockIdx.x * 8 + warp;
        const float* wr = W2 + (size_t)k * CDIM;
        float acc[EDIM];
#pragma unroll
        for (int e = 0; e < EDIM; e++) acc[e] = 0.f;
        for (int c = lane; c < CDIM; c += 32) {
            float wv = wr[c];
#pragma unroll
            for (int e = 0; e < EDIM; e++) acc[e] += wv * tqs[e][c];
        }
#pragma unroll
        for (int off = 16; off >= 1; off >>= 1)
#pragma unroll
            for (int e = 0; e < EDIM; e++)
                acc[e] += __shfl_xor_sync(0xffffffffu, acc[e], off);
        if (lane < EDIM) {
            float v = 0.f;
#pragma unroll
            for (int e = 0; e < EDIM; e++) if (lane == e) v = acc[e];
            Wf[(size_t)k * EDIM + lane] = v;
        }
    } else {
        if (warp < EDIM) {
            float a = 0.f;
            for (int c = lane; c < CDIM; c += 32) a += b2[c] * tqs[warp][c];
#pragma unroll
            for (int off = 16; off >= 1; off >>= 1)
                a += __shfl_xor_sync(0xffffffffu, a, off);
            if (lane == 0) b2tq[warp] = a;
        }
    }
}

// ---------------- GEMM1 stage loader (512 threads, BK=32) ----------------
// A: 128 rows x 4 chunks x 2 arrays -> 1 chunk/thread/array
// B: 256 rows x 4 chunks x 2 arrays -> 2 chunks/thread/array
__device__ __forceinline__ void issue_stage(
    const __nv_bfloat16* __restrict__ Ah, const __nv_bfloat16* __restrict__ Al,
    const __nv_bfloat16* __restrict__ Bh, const __nv_bfloat16* __restrict__ Bl,
    uint32_t stage_base, int kblk, int tid)
{
    const size_t kb = (size_t)kblk * 32;
    {
        int r = tid >> 2, ch = tid & 3;
        uint32_t so = stage_base + r * ROWB + ch * 16;
        size_t go = (size_t)r * CDIM + kb + ch * 8;
        cpa16(so + OFF_AH, Ah + go);
        cpa16(so + OFF_AL, Al + go);
    }
#pragma unroll
    for (int j = 0; j < 2; j++) {
        int idx = tid + j * 512;
        int r = idx >> 2, ch = idx & 3;
        uint32_t so = stage_base + r * ROWB + ch * 16;
        size_t go = (size_t)r * CDIM + kb + ch * 8;
        cpa16(so + OFF_BH, Bh + go);
        cpa16(so + OFF_BL, Bl + go);
    }
}

// ---------------- fused GEMM1 + scores partial ----------------
// 512 threads, 16 warps (4 warp_m x 4 warp_n), warp tile 32x64, CTA tile 128x256.
__global__ void __launch_bounds__(512, 1)
gemm_fused(const __nv_bfloat16* __restrict__ Ah, const __nv_bfloat16* __restrict__ Al,
           const __nv_bfloat16* __restrict__ Bh, const __nv_bfloat16* __restrict__ Bl,
           const float* __restrict__ bias, const float* __restrict__ w2tqf,
           float* __restrict__ spart)
{
    extern __shared__ __align__(128) char smem[];
    const uint32_t sb = smem_u32(smem) + SM_ST;
    float* w2s = (float*)(smem + SM_W2);        // [256][8]
    const int tid = threadIdx.x;
    const int wid = tid >> 5, lane = tid & 31;
    const int warp_m = wid >> 2, warp_n = wid & 3;   // 4 x 4 warp grid, 32x64 per warp
    const int bx = blockIdx.x, by = blockIdx.y;
    constexpr int NCH = CDIM / 32;

    const __nv_bfloat16* At_h = Ah + (size_t)(by * 128) * CDIM;
    const __nv_bfloat16* At_l = Al + (size_t)(by * 128) * CDIM;
    const __nv_bfloat16* Bt_h = Bh + (size_t)(bx * 256) * CDIM;
    const __nv_bfloat16* Bt_l = Bl + (size_t)(bx * 256) * CDIM;

    // load this CTA's w2tq slice (256 cols x 8 experts, fp32)
    {
        const float4* src = (const float4*)(w2tqf + (size_t)(bx * 256) * EDIM);
        float4* dst = (float4*)w2s;
        for (int i = tid; i < 256 * EDIM / 4; i += 512) dst[i] = src[i];
    }

    float acc[2][8][4];
#pragma unroll
    for (int i = 0; i < 2; i++)
#pragma unroll
        for (int j = 0; j < 8; j++)
#pragma unroll
            for (int k = 0; k < 4; k++) acc[i][j][k] = 0.f;

    issue_stage(At_h, At_l, Bt_h, Bt_l, sb + 0 * STAGE, 0, tid);
    CP_COMMIT();
    issue_stage(At_h, At_l, Bt_h, Bt_l, sb + 1 * STAGE, 1, tid);
    CP_COMMIT();
    CP_WAIT1();
    __syncthreads();

    const int aRow = warp_m * 32 + (lane & 15);
    const int aCol16 = (lane >> 4) * 16;
    const int bRow = warp_n * 64 + (lane & 7) + ((lane >> 4) << 3);
    const int bCol16 = ((lane >> 3) & 1) * 16;

#pragma unroll 1
    for (int c = 0; c < NCH; c++) {
        const uint32_t st = sb + (c % 3) * STAGE;
        if (c + 2 < NCH)
            issue_stage(At_h, At_l, Bt_h, Bt_l, sb + ((c + 2) % 3) * STAGE, c + 2, tid);
        CP_COMMIT();

#pragma unroll
        for (int ks = 0; ks < 2; ks++) {
            uint32_t ahf[2][4], alf[2][4];
#pragma unroll
            for (int mt = 0; mt < 2; mt++) {
                uint32_t ad = st + OFF_AH + (uint32_t)(aRow + mt * 16) * ROWB + aCol16 + ks * 32;
                ldsm4(ahf[mt], ad);
                ldsm4(alf[mt], ad + (OFF_AL - OFF_AH));
            }
            // B fragments loaded per 16-row group, consumed immediately (low reg pressure)
#pragma unroll
            for (int nh = 0; nh < 4; nh++) {
                uint32_t bh[4], bl[4];
                uint32_t bd = st + OFF_BH + (uint32_t)(bRow + nh * 16) * ROWB + bCol16 + ks * 32;
                ldsm4(bh, bd);
                ldsm4(bl, bd + (OFF_BL - OFF_BH));
#pragma unroll
                for (int mt = 0; mt < 2; mt++)
#pragma unroll
                    for (int half = 0; half < 2; half++) {
                        const int nt = nh * 2 + half;
                        const uint32_t* bh2 = &bh[half * 2];
                        const uint32_t* bl2 = &bl[half * 2];
                        mma16816(acc[mt][nt], ahf[mt], bh2);
                        mma16816(acc[mt][nt], ahf[mt], bl2);
                        mma16816(acc[mt][nt], alf[mt], bh2);
                    }
            }
        }
        CP_WAIT1();
        __syncthreads();
    }

    // ---- fused epilogue: gelu + partial scores, no h stores ----
    float p[4][EDIM];
#pragma unroll
    for (int r = 0; r < 4; r++)
#pragma unroll
        for (int e = 0; e < EDIM; e++) p[r][e] = 0.f;

#pragma unroll
    for (int mt = 0; mt < 2; mt++)
#pragma unroll
        for (int nt = 0; nt < 8; nt++) {
            const int col_local = warp_n * 64 + nt * 8 + (lane & 3) * 2;
            const int col = bx * 256 + col_local;
            const float bv0 = __ldg(bias + col), bv1 = __ldg(bias + col + 1);
            const float* w0 = w2s + col_local * EDIM;
            const float* w1 = w2s + (col_local + 1) * EDIM;
#pragma unroll
            for (int half = 0; half < 2; half++) {
                const int ri = mt * 2 + half;
                float v0 = gelu_exact(acc[mt][nt][half * 2 + 0] + bv0);
                float v1 = gelu_exact(acc[mt][nt][half * 2 + 1] + bv1);
#pragma unroll
                for (int e = 0; e < EDIM; e++)
                    p[ri][e] += v0 * w0[e] + v1 * w1[e];
            }
        }

    // reduce across the 4 lanes of each quad (disjoint cols, same rows)
#pragma unroll
    for (int off = 1; off <= 2; off <<= 1)
#pragma unroll
        for (int r = 0; r < 4; r++)
#pragma unroll
            for (int e = 0; e < EDIM; e++)
                p[r][e] += __shfl_xor_sync(0xffffffffu, p[r][e], off);

    // cross-warp_n reduction through (now free) stage smem: sp[4][128][8]
    float* sp = (float*)(smem + SM_ST);
    __syncthreads();   // all mainloop smem reads complete; safe to reuse
    if ((lane & 3) == 0) {
#pragma unroll
        for (int ri = 0; ri < 4; ri++) {
            const int mt = ri >> 1, half = ri & 1;
            const int row_local = warp_m * 32 + mt * 16 + (lane >> 2) + half * 8;
#pragma unroll
            for (int e = 0; e < EDIM; e++)
                sp[(warp_n * 128 + row_local) * EDIM + e] = p[ri][e];
        }
    }
    __syncthreads();

    // final: sum 4 warp_n slices, write partial to g_spart[bx]
    for (int idx = tid; idx < 128 * EDIM; idx += 512) {
        float s = sp[idx] + sp[128 * EDIM + idx] + sp[256 * EDIM + idx] + sp[384 * EDIM + idx];
        spart[((size_t)bx * MTOT + by * 128) * EDIM + idx] = s;
    }
}

// ---------------- deterministic reduce over hdim slices ----------------
__global__ void __launch_bounds__(256)
reduce_scores(const float* __restrict__ spart, float* __restrict__ S, int n)
{
    int idx = blockIdx.x * blockDim.x + threadIdx.x;
    if (idx >= n) return;
    float s = 0.f;
#pragma unroll
    for (int b = 0; b < NXSL; b++)
        s += spart[(size_t)b * n + idx];
    S[idx] = s;
}

// ---------------- routing tail (unchanged from R12 pass) ----------------
__global__ void __launch_bounds__(256)
route_kernel(const float* __restrict__ S, const float* __restrict__ x,
             const float* __restrict__ noise,
             const float* __restrict__ nw, const float* __restrict__ nb,
             const float* __restrict__ temp_p, const float* __restrict__ b2tq,
             float* __restrict__ out_router, float* __restrict__ out_idx, int M)
{
    __shared__ float nws[CDIM];
    __shared__ float b2s[EDIM];
    for (int i = threadIdx.x; i < CDIM; i += blockDim.x) nws[i] = nw[i];
    if (threadIdx.x < EDIM) b2s[threadIdx.x] = b2tq[threadIdx.x];
    __syncthreads();

    const int lane = threadIdx.x & 31;
    const int warp = threadIdx.x >> 5;
    const float temp = *temp_p;
    const float nbv  = *nb;

    for (int t = blockIdx.x * 8 + warp; t < M; t += gridDim.x * 8) {
        const float* xr = x + (size_t)t * CDIM;
        float accg = 0.f;
        for (int j = lane; j < CDIM; j += 32) accg += xr[j] * nws[j];
#pragma unroll
        for (int off = 16; off >= 1; off >>= 1)
            accg += __shfl_xor_sync(0xffffffffu, accg, off);

        float gate = 1.f / (1.f + expf(-(accg + nbv)));

        const float4* sp = (const float4*)(S + (size_t)t * EDIM);
        float4 s0 = sp[0], s1 = sp[1];
        float sc[EDIM] = { s0.x, s0.y, s0.z, s0.w, s1.x, s1.y, s1.z, s1.w };

        float noisy[EDIM];
#pragma unroll
        for (int e = 0; e < EDIM; e++)
            noisy[e] = sc[e] + b2s[e] + temp * noise[(size_t)t * EDIM + e] * gate;

        int i0 = 0; float v0 = noisy[0];
#pragma unroll
        for (int e = 1; e < EDIM; e++)
            if (noisy[e] > v0) { v0 = noisy[e]; i0 = e; }
        int i1 = -1; float v1 = -INFINITY;
#pragma unroll
        for (int e = 0; e < EDIM; e++)
            if (e != i0 && noisy[e] > v1) { v1 = noisy[e]; i1 = e; }

        float inv = 1.f / (temp + 1e-6f);
        float e1 = expf((v1 - v0) * inv);
        float denom = 1.f + e1;
        float p0 = 1.f / denom;
        float p1 = e1 / denom;

        if (lane < EDIM) {
            float pv = (lane == i0) ? p0 : ((lane == i1) ? p1 : 0.f);
            out_router[(size_t)t * EDIM + lane] = pv;
        }
        if (out_idx != nullptr && lane == 0) {
            out_idx[(size_t)t * 2 + 0] = (float)i0;
            out_idx[(size_t)t * 2 + 1] = (float)i1;
        }
    }
}

// ---------------- launch ----------------
extern "C" void kernel_launch(void* const* d_in, const int* in_sizes, int n_in,
                              void* d_out, int out_size)
{
    const float* x     = (const float*)d_in[0];
    const float* noise = (const float*)d_in[1];
    const float* W1    = (const float*)d_in[2];
    const float* b1    = (const float*)d_in[3];
    const float* W2    = (const float*)d_in[4];
    const float* b2    = (const float*)d_in[5];
    const float* tq    = (const float*)d_in[6];
    const float* nw    = (const float*)d_in[7];
    const float* nb    = (const float*)d_in[8];
    const float* temp  = (const float*)d_in[9];

    const int M = in_sizes[0] / CDIM;   // 32768

    __nv_bfloat16 *xh, *xl, *w1h, *w1l;
    float *w2tqf, *scores, *spart, *b2tqp;
    cudaGetSymbolAddress((void**)&xh,  g_xh);    cudaGetSymbolAddress((void**)&xl,  g_xl);
    cudaGetSymbolAddress((void**)&w1h, g_w1h);   cudaGetSymbolAddress((void**)&w1l, g_w1l);
    cudaGetSymbolAddress((void**)&w2tqf, g_w2tqf);
    cudaGetSymbolAddress((void**)&scores, g_scores);
    cudaGetSymbolAddress((void**)&spart, g_spart);
    cudaGetSymbolAddress((void**)&b2tqp, g_b2tq);

    cudaFuncSetAttribute(gemm_fused, cudaFuncAttributeMaxDynamicSharedMemorySize, SMEM_TOT);

    // prep: split x, transpose+split W1, fold W2 into tq (fp32)
    int n4 = (M * CDIM) / 4;
    split_x_kernel<<<(n4 + 255) / 256, 256>>>(x, xh, xl, n4);
    tsplit_kernel<<<dim3(HDIM / 32, CDIM / 32), dim3(32, 32)>>>(W1, w1h, w1l, CDIM, HDIM);
    w2tq_kernel<<<513, 256>>>(W2, tq, b2, w2tqf, b2tqp);

    // fused GEMM1 + scores partials (128x256 tile, 16 warps)
    gemm_fused<<<dim3(HDIM / 256, M / 128), 512, SMEM_TOT>>>(
        xh, xl, w1h, w1l, b1, w2tqf, spart);

    // deterministic reduction over the 16 hdim slices
    reduce_scores<<<(M * EDIM + 255) / 256, 256>>>(spart, scores, M * EDIM);

    float* out = (float*)d_out;
    float* out_router = out;
    float* out_idx = nullptr;
    if (out_size >= M * EDIM + M * 2)
        out_idx = out + (size_t)M * EDIM;

    route_kernel<<<M / 8, 256>>>(scores, x, noise, nw, nb, temp, b2tqp,
                                 out_router, out_idx, M);
}